// round 4
// baseline (speedup 1.0000x reference)
#include <cuda_runtime.h>

#define BATCH 32
#define KC 16
#define TIMESTEPS 8

// Membrane arena + activation ping-pong + split-K scratch.
__device__ float g_mem[8257536];
__device__ float g_bufA[2097152];
__device__ float g_bufB[2097152];
__device__ float g_bufC[2097152];
__device__ float g_scratch[1048576];

struct ConvP {
    const float* __restrict__ in;
    const float* __restrict__ w;
    float*       out;
    float*       mem;
    const float* __restrict__ res;
    const float* __restrict__ mask;
    const float* __restrict__ thr;
    const float* __restrict__ leak;
    float*       scratch;
    int li;
    int Cin, Hin, Win;
    int Cout, Hout, Wout;
    int mode;      // 0 = raw store, 1 = fused LIF, 2 = split-K partial to scratch
    int Kper;      // K-range per z-split
    int N;         // BATCH*Hout*Wout
};

// ============================================================================
// Unified conv kernel: 64co x 128pos tile, 128 threads, 8x8 per-thread block.
// 1.0 B smem per FMA (balanced against 128B/cyc crossbar).
// Split-K over blockIdx.z.
// ============================================================================
template<int KH, int STRIDE, int PAD>
__global__ __launch_bounds__(128) void conv8(ConvP p) {
    __shared__ __align__(16) float As[KC][64];
    __shared__ __align__(16) float Bs[KC][128];

    const int tid = threadIdx.x;
    const int tx = tid & 15;       // pos group: 16 groups x 8 pos
    const int ty = tid >> 4;       // co group:   8 groups x 8 co
    const int pos0 = blockIdx.x * 128;
    const int co0  = blockIdx.y * 64;
    const int HW = p.Hout * p.Wout;
    const int KK = KH * KH;
    const int K  = p.Cin * KK;
    const int kstart = blockIdx.z * p.Kper;
    const int kend   = (kstart + p.Kper < K) ? kstart + p.Kper : K;

    // A loader: lm = co-in-tile (0..63), 8 consecutive k per thread
    const int lm  = tid >> 1;
    const int lkq = (tid & 1) * 8;
    const float* __restrict__ wrow = p.w + (size_t)(co0 + lm) * K;

    // B loader: lp = pos-in-tile (0..127), 16 k per thread
    const int lp  = tid;
    const int pp  = pos0 + lp;
    const int pb  = pp / HW;
    const int phw = pp - pb * HW;
    const int py  = phw / p.Wout;
    const int px  = phw - py * p.Wout;
    const int iy0 = py * STRIDE - PAD;
    const int ix0 = px * STRIDE - PAD;
    const float* __restrict__ inb = p.in + (size_t)pb * p.Cin * p.Hin * p.Win;

    float acc[8][8];
#pragma unroll
    for (int i = 0; i < 8; i++)
#pragma unroll
        for (int j = 0; j < 8; j++) acc[i][j] = 0.f;

    float ra[8], rb[16];

    auto loadA = [&](int k0) {
#pragma unroll
        for (int i = 0; i < 8; i++) {
            int kk = k0 + lkq + i;
            ra[i] = (kk < kend) ? __ldg(wrow + kk) : 0.f;
        }
    };
    auto loadB = [&](int k0) {
#pragma unroll
        for (int i = 0; i < 16; i++) {
            int kk = k0 + i;
            float v = 0.f;
            if (kk < kend) {
                int ci = kk / KK;                  // KK compile-time constant
                int r  = kk - ci * KK;
                int ky = r / KH;
                int kx = r - ky * KH;
                int iy = iy0 + ky, ix = ix0 + kx;
                if (iy >= 0 && iy < p.Hin && ix >= 0 && ix < p.Win)
                    v = __ldg(inb + ((size_t)ci * p.Hin + iy) * p.Win + ix);
            }
            rb[i] = v;
        }
    };

    loadA(kstart); loadB(kstart);
    for (int k0 = kstart; k0 < kend; k0 += KC) {
#pragma unroll
        for (int i = 0; i < 8; i++) As[lkq + i][lm] = ra[i];
#pragma unroll
        for (int i = 0; i < 16; i++) Bs[i][lp] = rb[i];
        __syncthreads();
        if (k0 + KC < kend) { loadA(k0 + KC); loadB(k0 + KC); }
#pragma unroll
        for (int k = 0; k < KC; k++) {
            const float4 a0 = *(const float4*)&As[k][ty * 8];
            const float4 a1 = *(const float4*)&As[k][ty * 8 + 4];
            const float4 b0 = *(const float4*)&Bs[k][tx * 8];
            const float4 b1 = *(const float4*)&Bs[k][tx * 8 + 4];
            const float av[8] = {a0.x, a0.y, a0.z, a0.w, a1.x, a1.y, a1.z, a1.w};
            const float bv[8] = {b0.x, b0.y, b0.z, b0.w, b1.x, b1.y, b1.z, b1.w};
#pragma unroll
            for (int i = 0; i < 8; i++)
#pragma unroll
                for (int j = 0; j < 8; j++)
                    acc[i][j] = fmaf(av[i], bv[j], acc[i][j]);
        }
        __syncthreads();
    }

    // ---- epilogue ----
    if (p.mode == 2) {
        size_t base = ((size_t)blockIdx.z * p.Cout + co0 + ty * 8) * p.N
                      + pos0 + tx * 8;
#pragma unroll
        for (int i = 0; i < 8; i++) {
#pragma unroll
            for (int j = 0; j < 8; j++)
                p.scratch[base + (size_t)i * p.N + j] = acc[i][j];
        }
        return;
    }

    float th = 1.f, lkf = 1.f;
    if (p.mode == 1) { th = p.thr[p.li]; lkf = p.leak[p.li]; }

#pragma unroll
    for (int j = 0; j < 8; j++) {
        int posb = pos0 + tx * 8 + j;
        int b  = posb / HW;
        int hw = posb - b * HW;
        size_t base = ((size_t)b * p.Cout + co0 + ty * 8) * HW + hw;
#pragma unroll
        for (int i = 0; i < 8; i++) {
            size_t g = base + (size_t)i * HW;
            float d = acc[i][j];
            if (p.mode == 0) {
                p.out[g] = d;
            } else {
                if (p.res) d += p.res[g];
                float m  = lkf * p.mem[g] + d;
                float mt = m / th - 1.f;
                float s  = (mt > 0.f) ? 1.f : 0.f;
                p.mem[g] = m - th * s;
                float o = s;
                if (p.mask) o *= p.mask[g];
                p.out[g] = o;
            }
        }
    }
}

// Combine split-K partials + residual + LIF.
__global__ void combine_lif(const float* __restrict__ scratch, int S, int Cout,
                            int N, int HW,
                            const float* __restrict__ res,
                            const float* __restrict__ mask,
                            float* mem, float* out,
                            const float* __restrict__ thr,
                            const float* __restrict__ leak, int li) {
    int idx = blockIdx.x * blockDim.x + threadIdx.x;
    int total = Cout * N;
    if (idx >= total) return;
    int co  = idx / N;
    int pos = idx - co * N;
    float d = 0.f;
    for (int s = 0; s < S; s++)
        d += scratch[((size_t)s * Cout + co) * N + pos];
    int b = pos / HW, hw = pos - b * HW;
    size_t g = ((size_t)b * Cout + co) * HW + hw;
    if (res) d += res[g];
    float th = thr[li], lkf = leak[li];
    float m  = lkf * mem[g] + d;
    float mt = m / th - 1.f;
    float s_ = (mt > 0.f) ? 1.f : 0.f;
    mem[g] = m - th * s_;
    float o = s_;
    if (mask) o *= mask[g];
    out[g] = o;
}

__global__ void zero_kernel(float* mem, int n, float* out, int nout) {
    int i = blockIdx.x * blockDim.x + threadIdx.x;
    if (i < n) mem[i] = 0.f;
    if (i < nout) out[i] = 0.f;
}

__global__ void avgpool2_kernel(const float* __restrict__ in, float* out,
                                int C, int H, int W) {
    int Ho = H >> 1, Wo = W >> 1;
    int total = BATCH * C * Ho * Wo;
    int idx = blockIdx.x * blockDim.x + threadIdx.x;
    if (idx >= total) return;
    int x = idx % Wo; int t = idx / Wo;
    int y = t % Ho;   t /= Ho;
    int c = t % C;    int b = t / C;
    const float* pp = in + (((size_t)b * C + c) * H + y * 2) * W + x * 2;
    out[idx] = 0.25f * (pp[0] + pp[1] + pp[W] + pp[W + 1]);
}

__global__ void fc_acc_kernel(const float* __restrict__ o,
                              const float* __restrict__ wfc, float* out) {
    int bk = blockIdx.x;
    int b = bk / 10, k = bk % 10;
    const float* op = o + (size_t)b * 2048;
    const float* wp = wfc + (size_t)k * 2048;
    float s = 0.f;
    for (int j = threadIdx.x; j < 2048; j += 128) s += op[j] * wp[j];
    __shared__ float red[128];
    red[threadIdx.x] = s;
    __syncthreads();
    for (int st = 64; st > 0; st >>= 1) {
        if (threadIdx.x < st) red[threadIdx.x] += red[threadIdx.x + st];
        __syncthreads();
    }
    if (threadIdx.x == 0) out[b * 10 + k] += red[0];
}

// ============================================================================
// Host side
// ============================================================================

static ConvP mkp(const float* in, const float* w, float* out, float* mem,
                 const float* res, const float* mask,
                 const float* thr, const float* leak, float* scratch, int li,
                 int Cin, int Hin, int Win, int Cout, int Hout, int Wout,
                 int mode, int Kper) {
    ConvP p;
    p.in = in; p.w = w; p.out = out; p.mem = mem; p.res = res; p.mask = mask;
    p.thr = thr; p.leak = leak; p.scratch = scratch; p.li = li;
    p.Cin = Cin; p.Hin = Hin; p.Win = Win;
    p.Cout = Cout; p.Hout = Hout; p.Wout = Wout;
    p.mode = mode; p.Kper = Kper; p.N = BATCH * Hout * Wout;
    return p;
}

extern "C" void kernel_launch(void* const* d_in, const int* in_sizes, int n_in,
                              void* d_out, int out_size) {
    const float* x      = (const float*)d_in[0];
    const float* w_pre0 = (const float*)d_in[1];
    const float* w_pre1 = (const float*)d_in[2];
    const float* w_pre2 = (const float*)d_in[3];
    const float* w1a    = (const float*)d_in[4];
    const float* w1b    = (const float*)d_in[5];
    const float* w2a    = (const float*)d_in[6];
    const float* w2b    = (const float*)d_in[7];
    const float* w2i    = (const float*)d_in[8];
    const float* w3a    = (const float*)d_in[9];
    const float* w3b    = (const float*)d_in[10];
    const float* w3i    = (const float*)d_in[11];
    const float* w4a    = (const float*)d_in[12];
    const float* w4b    = (const float*)d_in[13];
    const float* w4i    = (const float*)d_in[14];
    const float* w_fc   = (const float*)d_in[15];
    const float* thr    = (const float*)d_in[16];
    const float* leak   = (const float*)d_in[17];
    const float* mask2  = (const float*)d_in[18];
    const float* mask5  = (const float*)d_in[19];
    const float* mask9  = (const float*)d_in[20];
    const float* mask11 = (const float*)d_in[21];
    const float* mask13 = (const float*)d_in[22];
    const float* mask15 = (const float*)d_in[23];

    float *memBase, *bufA, *bufB, *bufC, *scr;
    cudaGetSymbolAddress((void**)&memBase, g_mem);
    cudaGetSymbolAddress((void**)&bufA, g_bufA);
    cudaGetSymbolAddress((void**)&bufB, g_bufB);
    cudaGetSymbolAddress((void**)&bufC, g_bufC);
    cudaGetSymbolAddress((void**)&scr, g_scratch);
    float* out = (float*)d_out;

    float* m0  = memBase + 0;
    float* m1  = memBase + 2097152;
    float* m2  = memBase + 4194304;
    float* m3  = memBase + 6291456;
    float* m4  = memBase + 6815744;
    float* m5  = memBase + 7340032;
    float* m6  = memBase + 7602176;
    float* m7  = memBase + 7864320;
    float* m8  = memBase + 7995392;
    float* m9  = memBase + 8126464;
    float* m10 = memBase + 8192000;

    zero_kernel<<<(8257536 + 255) / 256, 256>>>(memBase, 8257536, out, 320);

    for (int t = 0; t < TIMESTEPS; t++) {
        ConvP p;
        // ---- pre_process: three 3x3 convs @32x32, Cout=64, N=32768 ----
        p = mkp(x, w_pre0, bufA, m0, nullptr, mask2, thr, leak, scr, 0,
                3, 32, 32, 64, 32, 32, 1, 27);
        conv8<3,1,1><<<dim3(256, 1, 1), 128>>>(p);
        p = mkp(bufA, w_pre1, bufB, m1, nullptr, mask5, thr, leak, scr, 1,
                64, 32, 32, 64, 32, 32, 1, 576);
        conv8<3,1,1><<<dim3(256, 1, 1), 128>>>(p);
        p = mkp(bufB, w_pre2, bufA, m2, nullptr, nullptr, thr, leak, scr, 2,
                64, 32, 32, 64, 32, 32, 1, 576);
        conv8<3,1,1><<<dim3(256, 1, 1), 128>>>(p);
        avgpool2_kernel<<<(BATCH*64*16*16 + 255)/256, 256>>>(bufA, bufB, 64, 32, 32);

        // ---- layer1 (identity shortcut), inp = bufB, 16x16, Cout=64, N=8192 ----
        p = mkp(bufB, w1a, nullptr, nullptr, nullptr, nullptr, thr, leak, scr, 0,
                64, 16, 16, 64, 16, 16, 2, 288);               // K=576, S=2
        conv8<3,1,1><<<dim3(64, 1, 2), 128>>>(p);
        combine_lif<<<(64*8192 + 255)/256, 256>>>(scr, 2, 64, 8192, 256,
                nullptr, mask9, m3, bufA, thr, leak, 3);
        p = mkp(bufA, w1b, nullptr, nullptr, nullptr, nullptr, thr, leak, scr, 0,
                64, 16, 16, 64, 16, 16, 2, 288);
        conv8<3,1,1><<<dim3(64, 1, 2), 128>>>(p);
        combine_lif<<<(64*8192 + 255)/256, 256>>>(scr, 2, 64, 8192, 256,
                bufB, nullptr, m4, bufC, thr, leak, 4);

        // ---- layer2, inp = bufC, out 8x8, Cout=128, N=2048 ----
        p = mkp(bufC, w2a, nullptr, nullptr, nullptr, nullptr, thr, leak, scr, 0,
                64, 16, 16, 128, 8, 8, 2, 144);                // K=576, S=4
        conv8<3,2,1><<<dim3(16, 2, 4), 128>>>(p);
        combine_lif<<<(128*2048 + 255)/256, 256>>>(scr, 4, 128, 2048, 64,
                nullptr, mask11, m5, bufA, thr, leak, 5);
        p = mkp(bufC, w2i, bufB, nullptr, nullptr, nullptr, thr, leak, scr, 0,
                64, 16, 16, 128, 8, 8, 0, 64);
        conv8<1,2,0><<<dim3(16, 2, 1), 128>>>(p);
        p = mkp(bufA, w2b, nullptr, nullptr, nullptr, nullptr, thr, leak, scr, 0,
                128, 8, 8, 128, 8, 8, 2, 288);                 // K=1152, S=4
        conv8<3,1,1><<<dim3(16, 2, 4), 128>>>(p);
        combine_lif<<<(128*2048 + 255)/256, 256>>>(scr, 4, 128, 2048, 64,
                bufB, nullptr, m6, bufC, thr, leak, 6);

        // ---- layer3, inp = bufC, out 4x4, Cout=256, N=512 ----
        p = mkp(bufC, w3a, nullptr, nullptr, nullptr, nullptr, thr, leak, scr, 0,
                128, 8, 8, 256, 4, 4, 2, 144);                 // K=1152, S=8
        conv8<3,2,1><<<dim3(4, 4, 8), 128>>>(p);
        combine_lif<<<(256*512 + 255)/256, 256>>>(scr, 8, 256, 512, 16,
                nullptr, mask13, m7, bufA, thr, leak, 7);
        p = mkp(bufC, w3i, bufB, nullptr, nullptr, nullptr, thr, leak, scr, 0,
                128, 8, 8, 256, 4, 4, 0, 128);
        conv8<1,2,0><<<dim3(4, 4, 1), 128>>>(p);
        p = mkp(bufA, w3b, nullptr, nullptr, nullptr, nullptr, thr, leak, scr, 0,
                256, 4, 4, 256, 4, 4, 2, 288);                 // K=2304, S=8
        conv8<3,1,1><<<dim3(4, 4, 8), 128>>>(p);
        combine_lif<<<(256*512 + 255)/256, 256>>>(scr, 8, 256, 512, 16,
                bufB, nullptr, m8, bufC, thr, leak, 8);

        // ---- layer4, inp = bufC, out 2x2, Cout=512, N=128 ----
        p = mkp(bufC, w4a, nullptr, nullptr, nullptr, nullptr, thr, leak, scr, 0,
                256, 4, 4, 512, 2, 2, 2, 144);                 // K=2304, S=16
        conv8<3,2,1><<<dim3(1, 8, 16), 128>>>(p);
        combine_lif<<<(512*128 + 255)/256, 256>>>(scr, 16, 512, 128, 4,
                nullptr, mask15, m9, bufA, thr, leak, 9);
        p = mkp(bufC, w4i, bufB, nullptr, nullptr, nullptr, thr, leak, scr, 0,
                256, 4, 4, 512, 2, 2, 0, 256);
        conv8<1,2,0><<<dim3(1, 8, 1), 128>>>(p);
        p = mkp(bufA, w4b, nullptr, nullptr, nullptr, nullptr, thr, leak, scr, 0,
                512, 2, 2, 512, 2, 2, 2, 288);                 // K=4608, S=16
        conv8<3,1,1><<<dim3(1, 8, 16), 128>>>(p);
        combine_lif<<<(512*128 + 255)/256, 256>>>(scr, 16, 512, 128, 4,
                bufB, nullptr, m10, bufC, thr, leak, 10);

        // ---- output accumulator ----
        fc_acc_kernel<<<320, 128>>>(bufC, w_fc, out);
    }
}

// round 5
// speedup vs baseline: 1.5546x; 1.5546x over previous
#include <cuda_runtime.h>

#define BATCH 32
#define KC 16
#define TIMESTEPS 8

// Membrane arena + activation ping-pong + split-K scratch + transposed weights.
__device__ float g_mem[8257536];
__device__ float g_bufA[2097152];
__device__ float g_bufB[2097152];
__device__ float g_bufC[2097152];
__device__ float g_scratch[2097152];
__device__ float g_wT[4966080];

struct ConvP {
    const float* __restrict__ in;
    const float* __restrict__ wT;     // [KK][Cin][Cout]
    float*       out;
    float*       mem;
    const float* __restrict__ res;
    const float* __restrict__ mask;
    const float* __restrict__ thr;
    const float* __restrict__ leak;
    float*       scratch;
    int li;
    int Cin, Hin, Win;
    int Cout, Hout, Wout;
    int mode;        // 0 raw, 1 fused LIF, 2 split-K partial
    int ccShift;     // nCC = Cin/16 = 1<<ccShift (1 for Cin=3)
    int nCCmask;
    int cTotal;      // KK * nCC chunks
    int cPerZ;
    int N;           // BATCH*Hout*Wout
};

// ============================================================================
// convT: 64co x 128pos tile, 256 threads, 4x8 per-thread block.
// 3x3 conv = 9 shifted 1x1 GEMMs over wT (no im2col div/mod in hot loop).
// Double-buffered smem, one sync per chunk. Split-K over blockIdx.z.
// ============================================================================
template<int KH, int STRIDE, int PAD>
__global__ __launch_bounds__(256) void convT(ConvP p) {
    __shared__ __align__(16) float As[2][KC][64];
    __shared__ __align__(16) float Bs[2][KC][128];

    const int tid = threadIdx.x;
    const int tx = tid & 15;
    const int ty = tid >> 4;
    const int pos0 = blockIdx.x * 128;
    const int co0  = blockIdx.y * 64;
    const int HW   = p.Hout * p.Wout;
    const int HWin = p.Hin * p.Win;

    // A loader: one float4 per thread. k row = tid>>4, co = (tid&15)*4.
    const int kA  = tid >> 4;
    const int coA = (tid & 15) * 4;

    // B loader: lp = tid&127 (pos), kq = (tid>>7)*8 (8 k's).
    const int lp = tid & 127;
    const int kq = (tid >> 7) * 8;
    const int pp  = pos0 + lp;
    const int pb  = pp / HW;
    const int phw = pp - pb * HW;
    const int py  = phw / p.Wout;
    const int px  = phw - py * p.Wout;
    const int iy0 = py * STRIDE - PAD;
    const int ix0 = px * STRIDE - PAD;
    const float* __restrict__ inb = p.in + (size_t)pb * p.Cin * HWin;

    const int c0 = blockIdx.z * p.cPerZ;
    int c1 = c0 + p.cPerZ; if (c1 > p.cTotal) c1 = p.cTotal;

    float4 ra;
    float rb[8];

    auto prefetch = [&](int c) {
        const int r   = c >> p.ccShift;
        const int ci0 = (c & p.nCCmask) << 4;
        const int ky  = r / KH;
        const int kx  = r - ky * KH;
        // A: wT[(r*Cin + ci)*Cout + co]
        const int ciA = ci0 + kA;
        if (ciA < p.Cin)
            ra = *(const float4*)(p.wT + ((size_t)r * p.Cin + ciA) * p.Cout + co0 + coA);
        else
            ra = make_float4(0.f, 0.f, 0.f, 0.f);
        // B: input[ci][iy][ix]
        const int iy = iy0 + ky, ix = ix0 + kx;
        const bool ok = (iy >= 0 && iy < p.Hin && ix >= 0 && ix < p.Win);
        const float* src = inb + (size_t)(ci0 + kq) * HWin + iy * p.Win + ix;
#pragma unroll
        for (int i = 0; i < 8; i++) {
            int ci = ci0 + kq + i;
            rb[i] = (ok && ci < p.Cin) ? __ldg(src + (size_t)i * HWin) : 0.f;
        }
    };

    float acc[4][8];
#pragma unroll
    for (int i = 0; i < 4; i++)
#pragma unroll
        for (int j = 0; j < 8; j++) acc[i][j] = 0.f;

    prefetch(c0);
    *(float4*)&As[0][kA][coA] = ra;
#pragma unroll
    for (int i = 0; i < 8; i++) Bs[0][kq + i][lp] = rb[i];

    int s = 0;
    for (int c = c0; c < c1; c++) {
        __syncthreads();
        const bool more = (c + 1 < c1);
        if (more) prefetch(c + 1);
#pragma unroll
        for (int k = 0; k < KC; k++) {
            const float4 a  = *(const float4*)&As[s][k][ty * 4];
            const float4 b0 = *(const float4*)&Bs[s][k][tx * 4];
            const float4 b1 = *(const float4*)&Bs[s][k][64 + tx * 4];
            const float av[4] = {a.x, a.y, a.z, a.w};
            const float bv[8] = {b0.x, b0.y, b0.z, b0.w, b1.x, b1.y, b1.z, b1.w};
#pragma unroll
            for (int i = 0; i < 4; i++)
#pragma unroll
                for (int j = 0; j < 8; j++)
                    acc[i][j] = fmaf(av[i], bv[j], acc[i][j]);
        }
        if (more) {
            *(float4*)&As[s ^ 1][kA][coA] = ra;
#pragma unroll
            for (int i = 0; i < 8; i++) Bs[s ^ 1][kq + i][lp] = rb[i];
        }
        s ^= 1;
    }

    // ---- epilogue ----
    if (p.mode == 2) {
#pragma unroll
        for (int h = 0; h < 2; h++) {
            int posb = pos0 + h * 64 + tx * 4;
            size_t base = ((size_t)blockIdx.z * p.Cout + co0 + ty * 4) * p.N + posb;
#pragma unroll
            for (int i = 0; i < 4; i++)
#pragma unroll
                for (int j = 0; j < 4; j++)
                    p.scratch[base + (size_t)i * p.N + j] = acc[i][h * 4 + j];
        }
        return;
    }

    float th = 1.f, lkf = 1.f;
    if (p.mode == 1) { th = p.thr[p.li]; lkf = p.leak[p.li]; }

#pragma unroll
    for (int h = 0; h < 2; h++) {
        int posb = pos0 + h * 64 + tx * 4;
        int b  = posb / HW;
        int hw = posb - b * HW;
#pragma unroll
        for (int i = 0; i < 4; i++) {
            size_t g = ((size_t)b * p.Cout + co0 + ty * 4 + i) * HW + hw;
#pragma unroll
            for (int j = 0; j < 4; j++) {
                float d = acc[i][h * 4 + j];
                size_t gi = g + j;
                if (p.mode == 0) {
                    p.out[gi] = d;
                } else {
                    if (p.res) d += p.res[gi];
                    float m  = lkf * p.mem[gi] + d;
                    float mt = m / th - 1.f;
                    float sp = (mt > 0.f) ? 1.f : 0.f;
                    p.mem[gi] = m - th * sp;
                    float o = sp;
                    if (p.mask) o *= p.mask[gi];
                    p.out[gi] = o;
                }
            }
        }
    }
}

// Weight transpose: w[Cout][Cin][KK] -> wT[KK][Cin][Cout]
__global__ void wt_kernel(const float* __restrict__ w, float* dst,
                          int Cout, int Cin, int KK) {
    int idx = blockIdx.x * blockDim.x + threadIdx.x;
    int total = Cout * Cin * KK;
    if (idx >= total) return;
    int co  = idx / (Cin * KK);
    int rem = idx - co * (Cin * KK);
    int ci  = rem / KK;
    int r   = rem - ci * KK;
    dst[((size_t)r * Cin + ci) * Cout + co] = w[idx];
}

// Combine split-K partials (+ optional residual/mask) + LIF.
__global__ void combine_lif(const float* __restrict__ scratch, int S, int Cout,
                            int N, int HW,
                            const float* __restrict__ res,
                            const float* __restrict__ mask,
                            float* mem, float* out,
                            const float* __restrict__ thr,
                            const float* __restrict__ leak, int li) {
    int idx = blockIdx.x * blockDim.x + threadIdx.x;
    int total = Cout * N;
    if (idx >= total) return;
    int co  = idx / N;
    int pos = idx - co * N;
    float d = 0.f;
    for (int s = 0; s < S; s++)
        d += scratch[((size_t)s * Cout + co) * N + pos];
    int b = pos / HW, hw = pos - b * HW;
    size_t g = ((size_t)b * Cout + co) * HW + hw;
    if (res) d += res[g];
    float th = thr[li], lkf = leak[li];
    float m  = lkf * mem[g] + d;
    float mt = m / th - 1.f;
    float s_ = (mt > 0.f) ? 1.f : 0.f;
    mem[g] = m - th * s_;
    float o = s_;
    if (mask) o *= mask[g];
    out[g] = o;
}

__global__ void zero_kernel(float* mem, int n, float* out, int nout) {
    int i = blockIdx.x * blockDim.x + threadIdx.x;
    if (i < n) mem[i] = 0.f;
    if (i < nout) out[i] = 0.f;
}

__global__ void avgpool2_kernel(const float* __restrict__ in, float* out,
                                int C, int H, int W) {
    int Ho = H >> 1, Wo = W >> 1;
    int total = BATCH * C * Ho * Wo;
    int idx = blockIdx.x * blockDim.x + threadIdx.x;
    if (idx >= total) return;
    int x = idx % Wo; int t = idx / Wo;
    int y = t % Ho;   t /= Ho;
    int c = t % C;    int b = t / C;
    const float* pp = in + (((size_t)b * C + c) * H + y * 2) * W + x * 2;
    out[idx] = 0.25f * (pp[0] + pp[1] + pp[W] + pp[W + 1]);
}

__global__ void fc_acc_kernel(const float* __restrict__ o,
                              const float* __restrict__ wfc, float* out) {
    int bk = blockIdx.x;
    int b = bk / 10, k = bk % 10;
    const float* op = o + (size_t)b * 2048;
    const float* wp = wfc + (size_t)k * 2048;
    float s = 0.f;
    for (int j = threadIdx.x; j < 2048; j += 128) s += op[j] * wp[j];
    __shared__ float red[128];
    red[threadIdx.x] = s;
    __syncthreads();
    for (int st = 64; st > 0; st >>= 1) {
        if (threadIdx.x < st) red[threadIdx.x] += red[threadIdx.x + st];
        __syncthreads();
    }
    if (threadIdx.x == 0) out[b * 10 + k] += red[0];
}

// ============================================================================
// Host side
// ============================================================================

static ConvP mkp(const float* in, const float* wT, float* out, float* mem,
                 const float* res, const float* mask,
                 const float* thr, const float* leak, float* scratch, int li,
                 int Cin, int Hin, int Win, int Cout, int Hout, int Wout,
                 int mode, int ccShift, int KK, int S) {
    ConvP p;
    p.in = in; p.wT = wT; p.out = out; p.mem = mem; p.res = res; p.mask = mask;
    p.thr = thr; p.leak = leak; p.scratch = scratch; p.li = li;
    p.Cin = Cin; p.Hin = Hin; p.Win = Win;
    p.Cout = Cout; p.Hout = Hout; p.Wout = Wout;
    p.mode = mode; p.ccShift = ccShift; p.nCCmask = (1 << ccShift) - 1;
    p.cTotal = KK << ccShift;
    p.cPerZ = (p.cTotal + S - 1) / S;
    p.N = BATCH * Hout * Wout;
    return p;
}

extern "C" void kernel_launch(void* const* d_in, const int* in_sizes, int n_in,
                              void* d_out, int out_size) {
    const float* x      = (const float*)d_in[0];
    const float* w_fc   = (const float*)d_in[15];
    const float* thr    = (const float*)d_in[16];
    const float* leak   = (const float*)d_in[17];
    const float* mask2  = (const float*)d_in[18];
    const float* mask5  = (const float*)d_in[19];
    const float* mask9  = (const float*)d_in[20];
    const float* mask11 = (const float*)d_in[21];
    const float* mask13 = (const float*)d_in[22];
    const float* mask15 = (const float*)d_in[23];

    float *memBase, *bufA, *bufB, *bufC, *scr, *wT;
    cudaGetSymbolAddress((void**)&memBase, g_mem);
    cudaGetSymbolAddress((void**)&bufA, g_bufA);
    cudaGetSymbolAddress((void**)&bufB, g_bufB);
    cudaGetSymbolAddress((void**)&bufC, g_bufC);
    cudaGetSymbolAddress((void**)&scr, g_scratch);
    cudaGetSymbolAddress((void**)&wT, g_wT);
    float* out = (float*)d_out;

    // ---- weight transposes (once per launch) ----
    // {input idx, offset, Cout, Cin, KK}
    static const int wdesc[14][5] = {
        {1,       0,  64,   3, 9},  // pre0
        {2,    1728,  64,  64, 9},  // pre1
        {3,   38592,  64,  64, 9},  // pre2
        {4,   75456,  64,  64, 9},  // w1a
        {5,  112320,  64,  64, 9},  // w1b
        {6,  149184, 128,  64, 9},  // w2a
        {7,  222912, 128, 128, 9},  // w2b
        {8,  370368, 128,  64, 1},  // w2i
        {9,  378560, 256, 128, 9},  // w3a
        {10, 673472, 256, 256, 9},  // w3b
        {11,1263296, 256, 128, 1},  // w3i
        {12,1296064, 512, 256, 9},  // w4a
        {13,2475712, 512, 512, 9},  // w4b
        {14,4835008, 512, 256, 1},  // w4i
    };
    for (int i = 0; i < 14; i++) {
        int total = wdesc[i][2] * wdesc[i][3] * wdesc[i][4];
        wt_kernel<<<(total + 255) / 256, 256>>>(
            (const float*)d_in[wdesc[i][0]], wT + wdesc[i][1],
            wdesc[i][2], wdesc[i][3], wdesc[i][4]);
    }
    const float* tpre0 = wT + 0;
    const float* tpre1 = wT + 1728;
    const float* tpre2 = wT + 38592;
    const float* t1a   = wT + 75456;
    const float* t1b   = wT + 112320;
    const float* t2a   = wT + 149184;
    const float* t2b   = wT + 222912;
    const float* t2i   = wT + 370368;
    const float* t3a   = wT + 378560;
    const float* t3b   = wT + 673472;
    const float* t3i   = wT + 1263296;
    const float* t4a   = wT + 1296064;
    const float* t4b   = wT + 2475712;
    const float* t4i   = wT + 4835008;

    float* m0  = memBase + 0;
    float* m1  = memBase + 2097152;
    float* m2  = memBase + 4194304;
    float* m3  = memBase + 6291456;
    float* m4  = memBase + 6815744;
    float* m5  = memBase + 7340032;
    float* m6  = memBase + 7602176;
    float* m7  = memBase + 7864320;
    float* m8  = memBase + 7995392;
    float* m9  = memBase + 8126464;
    float* m10 = memBase + 8192000;

    zero_kernel<<<(8257536 + 255) / 256, 256>>>(memBase, 8257536, out, 320);

    for (int t = 0; t < TIMESTEPS; t++) {
        ConvP p;
        // ---- pre_process: 3x3 convs @32x32, Cout=64, N=32768 ----
        p = mkp(x, tpre0, bufA, m0, nullptr, mask2, thr, leak, scr, 0,
                3, 32, 32, 64, 32, 32, 1, 0, 9, 1);
        convT<3,1,1><<<dim3(256, 1, 1), 256>>>(p);
        p = mkp(bufA, tpre1, bufB, m1, nullptr, mask5, thr, leak, scr, 1,
                64, 32, 32, 64, 32, 32, 1, 2, 9, 1);
        convT<3,1,1><<<dim3(256, 1, 1), 256>>>(p);
        p = mkp(bufB, tpre2, bufA, m2, nullptr, nullptr, thr, leak, scr, 2,
                64, 32, 32, 64, 32, 32, 1, 2, 9, 1);
        convT<3,1,1><<<dim3(256, 1, 1), 256>>>(p);
        avgpool2_kernel<<<(BATCH*64*16*16 + 255)/256, 256>>>(bufA, bufB, 64, 32, 32);

        // ---- layer1 (identity shortcut), inp = bufB, 16x16, Cout=64, N=8192 ----
        p = mkp(bufB, t1a, nullptr, nullptr, nullptr, nullptr, thr, leak, scr, 0,
                64, 16, 16, 64, 16, 16, 2, 2, 9, 2);
        convT<3,1,1><<<dim3(64, 1, 2), 256>>>(p);
        combine_lif<<<(64*8192 + 255)/256, 256>>>(scr, 2, 64, 8192, 256,
                nullptr, mask9, m3, bufA, thr, leak, 3);
        p = mkp(bufA, t1b, nullptr, nullptr, nullptr, nullptr, thr, leak, scr, 0,
                64, 16, 16, 64, 16, 16, 2, 2, 9, 2);
        convT<3,1,1><<<dim3(64, 1, 2), 256>>>(p);
        combine_lif<<<(64*8192 + 255)/256, 256>>>(scr, 2, 64, 8192, 256,
                bufB, nullptr, m4, bufC, thr, leak, 4);

        // ---- layer2, inp = bufC, out 8x8, Cout=128, N=2048 ----
        // shortcut partials into scratch slices [4..5]
        p = mkp(bufC, t2i, nullptr, nullptr, nullptr, nullptr, thr, leak,
                scr + (size_t)4*128*2048, 0,
                64, 16, 16, 128, 8, 8, 2, 2, 1, 2);
        convT<1,2,0><<<dim3(16, 2, 2), 256>>>(p);
        p = mkp(bufC, t2a, nullptr, nullptr, nullptr, nullptr, thr, leak, scr, 0,
                64, 16, 16, 128, 8, 8, 2, 2, 9, 4);
        convT<3,2,1><<<dim3(16, 2, 4), 256>>>(p);
        combine_lif<<<(128*2048 + 255)/256, 256>>>(scr, 4, 128, 2048, 64,
                nullptr, mask11, m5, bufA, thr, leak, 5);
        p = mkp(bufA, t2b, nullptr, nullptr, nullptr, nullptr, thr, leak, scr, 0,
                128, 8, 8, 128, 8, 8, 2, 3, 9, 4);
        convT<3,1,1><<<dim3(16, 2, 4), 256>>>(p);
        combine_lif<<<(128*2048 + 255)/256, 256>>>(scr, 6, 128, 2048, 64,
                nullptr, nullptr, m6, bufC, thr, leak, 6);

        // ---- layer3, inp = bufC, out 4x4, Cout=256, N=512 ----
        p = mkp(bufC, t3i, nullptr, nullptr, nullptr, nullptr, thr, leak,
                scr + (size_t)8*256*512, 0,
                128, 8, 8, 256, 4, 4, 2, 3, 1, 4);
        convT<1,2,0><<<dim3(4, 4, 4), 256>>>(p);
        p = mkp(bufC, t3a, nullptr, nullptr, nullptr, nullptr, thr, leak, scr, 0,
                128, 8, 8, 256, 4, 4, 2, 3, 9, 8);
        convT<3,2,1><<<dim3(4, 4, 8), 256>>>(p);
        combine_lif<<<(256*512 + 255)/256, 256>>>(scr, 8, 256, 512, 16,
                nullptr, mask13, m7, bufA, thr, leak, 7);
        p = mkp(bufA, t3b, nullptr, nullptr, nullptr, nullptr, thr, leak, scr, 0,
                256, 4, 4, 256, 4, 4, 2, 4, 9, 8);
        convT<3,1,1><<<dim3(4, 4, 8), 256>>>(p);
        combine_lif<<<(256*512 + 255)/256, 256>>>(scr, 12, 256, 512, 16,
                nullptr, nullptr, m8, bufC, thr, leak, 8);

        // ---- layer4, inp = bufC, out 2x2, Cout=512, N=128 ----
        p = mkp(bufC, t4i, nullptr, nullptr, nullptr, nullptr, thr, leak,
                scr + (size_t)16*512*128, 0,
                256, 4, 4, 512, 2, 2, 2, 4, 1, 8);
        convT<1,2,0><<<dim3(1, 8, 8), 256>>>(p);
        p = mkp(bufC, t4a, nullptr, nullptr, nullptr, nullptr, thr, leak, scr, 0,
                256, 4, 4, 512, 2, 2, 2, 4, 9, 16);
        convT<3,2,1><<<dim3(1, 8, 16), 256>>>(p);
        combine_lif<<<(512*128 + 255)/256, 256>>>(scr, 16, 512, 128, 4,
                nullptr, mask15, m9, bufA, thr, leak, 9);
        p = mkp(bufA, t4b, nullptr, nullptr, nullptr, nullptr, thr, leak, scr, 0,
                512, 2, 2, 512, 2, 2, 2, 5, 9, 16);
        convT<3,1,1><<<dim3(1, 8, 16), 256>>>(p);
        combine_lif<<<(512*128 + 255)/256, 256>>>(scr, 24, 512, 128, 4,
                nullptr, nullptr, m10, bufC, thr, leak, 10);

        // ---- output accumulator ----
        fc_acc_kernel<<<320, 128>>>(bufC, w_fc, out);
    }
}